// round 12
// baseline (speedup 1.0000x reference)
#include <cuda_runtime.h>
#include <cuda_fp16.h>
#include <cstdint>
#include <math.h>

#define BATCH 4096
#define HID   1024
#define NV    5120          // virtual N: [0,3072)=i,f,o  [3072,4096)=cand  [4096,5120)=s
#define KDIM  2048
#define BM    128
#define BN    128
#define BK    32
#define NSTG  3
#define KT    64            // 2048 / 32

#define ROWB  80            // smem row stride in bytes (64B data + 16B pad)
#define TILE_BYTES (128 * ROWB)              // 10240 per operand tile
#define STAGE_BYTES (2 * TILE_BYTES)         // A + B = 20480
#define SMEM_DYN (NSTG * STAGE_BYTES)        // 61440

// device scratch (static — no runtime allocation)
__device__ __half g_A[(size_t)BATCH * KDIM];    // 16 MB
__device__ __half g_B[(size_t)NV * KDIM];       // 20 MB
__device__ float  g_C[(size_t)BATCH * NV];      // 80 MB

// ---------------- helpers ----------------
__device__ __forceinline__ uint32_t smem_u32(const void* p) {
    uint32_t a;
    asm("{ .reg .u64 t; cvta.to.shared.u64 t, %1; cvt.u32.u64 %0, t; }" : "=r"(a) : "l"(p));
    return a;
}
__device__ __forceinline__ void cp_async16(uint32_t dst, const void* src) {
    asm volatile("cp.async.cg.shared.global [%0], [%1], 16;" :: "r"(dst), "l"(src));
}
__device__ __forceinline__ void cp_commit() { asm volatile("cp.async.commit_group;" ::: "memory"); }
__device__ __forceinline__ void cp_wait1()  { asm volatile("cp.async.wait_group 1;"  ::: "memory"); }

__device__ __forceinline__ void mma16816(float* c, const uint32_t* a, uint32_t b0, uint32_t b1) {
    asm volatile("mma.sync.aligned.m16n8k16.row.col.f32.f16.f16.f32 "
                 "{%0,%1,%2,%3}, {%4,%5,%6,%7}, {%8,%9}, {%0,%1,%2,%3};"
                 : "+f"(c[0]), "+f"(c[1]), "+f"(c[2]), "+f"(c[3])
                 : "r"(a[0]), "r"(a[1]), "r"(a[2]), "r"(a[3]), "r"(b0), "r"(b1));
}
__device__ __forceinline__ void ldsm_x4(uint32_t& r0, uint32_t& r1, uint32_t& r2, uint32_t& r3,
                                        uint32_t addr) {
    asm volatile("ldmatrix.sync.aligned.m8n8.x4.shared.b16 {%0,%1,%2,%3}, [%4];"
                 : "=r"(r0), "=r"(r1), "=r"(r2), "=r"(r3) : "r"(addr));
}

// ---------------- conversion kernels ----------------
__global__ __launch_bounds__(256) void convA_kernel(const float* __restrict__ x,
                                                    const float* __restrict__ h) {
    int idx = blockIdx.x * 256 + threadIdx.x;            // over (4096*2048)/4
    int v4 = idx * 4;
    if (v4 >= BATCH * KDIM) return;
    int m = v4 >> 11, k0 = v4 & 2047;
    float4 v = (k0 < 1024) ? *(const float4*)(x + (size_t)m * 1024 + k0)
                           : *(const float4*)(h + (size_t)m * 1024 + (k0 - 1024));
    __half2 p0 = __floats2half2_rn(v.x, v.y);
    __half2 p1 = __floats2half2_rn(v.z, v.w);
    *(__half2*)(g_A + (size_t)m * KDIM + k0)     = p0;
    *(__half2*)(g_A + (size_t)m * KDIM + k0 + 2) = p1;
}

__global__ __launch_bounds__(256) void convB_kernel(const float* __restrict__ Wi,
                                                    const float* __restrict__ Wf,
                                                    const float* __restrict__ Wo,
                                                    const float* __restrict__ Wxs,
                                                    const float* __restrict__ Wxg,
                                                    const float* __restrict__ Whg) {
    int idx = blockIdx.x * 256 + threadIdx.x;            // over (5120*2048)/4
    int v4 = idx * 4;
    if (v4 >= NV * KDIM) return;
    int n = v4 >> 11, k0 = v4 & 2047;
    float4 v;
    if (n < 3072) {
        const float* W = (n < 1024) ? Wi : (n < 2048) ? Wf : Wo;
        v = *(const float4*)(W + (size_t)(n & 1023) * 2048 + k0);
    } else if (n < 4096) {
        int rr = n - 3072;
        v = (k0 < 1024) ? *(const float4*)(Wxg + (size_t)rr * 1024 + k0)
                        : *(const float4*)(Whg + (size_t)rr * 1024 + (k0 - 1024));
    } else {
        int rr = n - 4096;
        v = (k0 < 1024) ? *(const float4*)(Wxs + (size_t)rr * 1024 + k0)
                        : make_float4(0.f, 0.f, 0.f, 0.f);
    }
    __half2 p0 = __floats2half2_rn(v.x, v.y);
    __half2 p1 = __floats2half2_rn(v.z, v.w);
    *(__half2*)(g_B + (size_t)n * KDIM + k0)     = p0;
    *(__half2*)(g_B + (size_t)n * KDIM + k0 + 2) = p1;
}

// ---------------- fp16 HMMA GEMM : 4 warps, 64x64 warp tiles ----------------
__global__ void __launch_bounds__(128, 3) gemm_kernel() {
    extern __shared__ char smem_dyn[];

    const int tid  = threadIdx.x;
    const int wid  = tid >> 5;
    const int lane = tid & 31;
    const int g    = lane >> 2;        // 0..7
    const int tig  = lane & 3;         // 0..3
    const int wm   = wid >> 1;         // 0..1 (rows wm*64)
    const int wn   = wid & 1;          // 0..1 (cols wn*64)
    const int bm0  = blockIdx.x * BM;
    const int n0   = blockIdx.y * BN;

    const uint32_t smem0 = smem_u32(smem_dyn);

    // ldmatrix lane addressing (byte offsets within a tile)
    // A x4 (m16 x k16): lanes 0-15 -> rows 0..15 col 0; lanes 16-31 -> rows 0..15 col 8
    const uint32_t a_lane_off = (uint32_t)((wm * 64 + (lane & 15)) * ROWB + (lane >> 4) * 16);
    // B x4 (two n8-tiles x k16): lanes 0-7: n 0..7 k0 | 8-15: n 0..7 k8 | 16-23: n 8..15 k0 | 24-31: n 8..15 k8
    const uint32_t b_lane_off = (uint32_t)((wn * 64 + ((lane >> 4) << 3) + (lane & 7)) * ROWB
                                           + (((lane >> 3) & 1) * 16));

    // stage loader: each thread loads one full 64B row of A and of B (4 chunks each)
    auto load_stage = [&](int s, int kk) {
        int kcol = kk * BK;
        uint32_t baseA = smem0 + s * STAGE_BYTES;
        uint32_t baseB = baseA + TILE_BYTES;
        const __half* srcA = g_A + (size_t)(bm0 + tid) * KDIM + kcol;
        const __half* srcB = g_B + (size_t)(n0  + tid) * KDIM + kcol;
        uint32_t rowoff = (uint32_t)tid * ROWB;
        #pragma unroll
        for (int ch = 0; ch < 4; ++ch) {
            cp_async16(baseA + rowoff + ch * 16, srcA + ch * 8);
            cp_async16(baseB + rowoff + ch * 16, srcB + ch * 8);
        }
        cp_commit();
    };

    float acc[4][8][4];
    #pragma unroll
    for (int i = 0; i < 4; ++i)
        #pragma unroll
        for (int j = 0; j < 8; ++j)
            #pragma unroll
            for (int t = 0; t < 4; ++t) acc[i][j][t] = 0.f;

    // prologue: stages 0,1
    load_stage(0, 0);
    load_stage(1, 1);

    for (int it = 0; it < KT; ++it) {
        int s = it % NSTG;
        cp_wait1();             // stage `it` resident (this thread's chunks)
        __syncthreads();        // all threads' chunks visible; prev compute done

        if (it + 2 < KT) load_stage((it + 2) % NSTG, it + 2);
        else cp_commit();       // keep group accounting exact at tail

        uint32_t Asb = smem0 + s * STAGE_BYTES;
        uint32_t Bsb = Asb + TILE_BYTES;

        #pragma unroll
        for (int ks = 0; ks < 2; ++ks) {
            const uint32_t kboff = ks * 32;      // 16 halves = 32 bytes
            uint32_t a[4][4];
            #pragma unroll
            for (int mt = 0; mt < 4; ++mt)
                ldsm_x4(a[mt][0], a[mt][1], a[mt][2], a[mt][3],
                        Asb + a_lane_off + mt * 16 * ROWB + kboff);
            #pragma unroll
            for (int j = 0; j < 4; ++j) {        // two n8-tiles per ldmatrix
                uint32_t b0, b1, b2, b3;
                ldsm_x4(b0, b1, b2, b3, Bsb + b_lane_off + j * 16 * ROWB + kboff);
                #pragma unroll
                for (int mt = 0; mt < 4; ++mt) {
                    mma16816(acc[mt][2 * j],     a[mt], b0, b1);
                    mma16816(acc[mt][2 * j + 1], a[mt], b2, b3);
                }
            }
        }
    }

    // write C tile
    #pragma unroll
    for (int mt = 0; mt < 4; ++mt) {
        #pragma unroll
        for (int in = 0; in < 8; ++in) {
            int row = bm0 + wm * 64 + mt * 16 + g;
            int col = n0 + wn * 64 + in * 8 + 2 * tig;
            float2 v0 = make_float2(acc[mt][in][0], acc[mt][in][1]);
            float2 v1 = make_float2(acc[mt][in][2], acc[mt][in][3]);
            *(float2*)(g_C + (size_t)row * NV + col)       = v0;
            *(float2*)(g_C + (size_t)(row + 8) * NV + col) = v1;
        }
    }
}

// ---------------- fused epilogue ----------------
__device__ __forceinline__ float sigmoidf_(float v) { return 1.0f / (1.0f + expf(-v)); }

__global__ __launch_bounds__(256)
void srul_epilogue_kernel(const float* __restrict__ c_prev,
                          const float* __restrict__ bi,
                          const float* __restrict__ bf,
                          const float* __restrict__ bo,
                          const float* __restrict__ bxs,
                          const float* __restrict__ bxg,
                          const float* __restrict__ bhg,
                          float* __restrict__ out)
{
    int idx = blockIdx.x * blockDim.x + threadIdx.x;
    int v = idx * 4;
    if (v >= BATCH * HID) return;
    int b = v >> 10;
    int j = v & 1023;

    const float* row = g_C + (size_t)b * NV;
    float4 ri = *(const float4*)(row + j);
    float4 rf = *(const float4*)(row + 1024 + j);
    float4 ro = *(const float4*)(row + 2048 + j);
    float4 rc = *(const float4*)(row + 3072 + j);
    float4 rs = *(const float4*)(row + 4096 + j);
    float4 vbi  = *(const float4*)(bi + j);
    float4 vbf  = *(const float4*)(bf + j);
    float4 vbo  = *(const float4*)(bo + j);
    float4 vbxs = *(const float4*)(bxs + j);
    float4 vbxg = *(const float4*)(bxg + j);
    float4 vbhg = *(const float4*)(bhg + j);
    float4 vcp  = *(const float4*)(c_prev + (size_t)b * 1024 + j);

    float4 outh, outc;
    const float* pri = &ri.x; const float* prf = &rf.x; const float* pro = &ro.x;
    const float* prc = &rc.x; const float* prs = &rs.x;
    const float* pbi = &vbi.x; const float* pbf = &vbf.x; const float* pbo = &vbo.x;
    const float* pbxs = &vbxs.x; const float* pbxg = &vbxg.x; const float* pbhg = &vbhg.x;
    const float* pcp = &vcp.x;
    float* ph = &outh.x; float* pc = &outc.x;

    #pragma unroll
    for (int t = 0; t < 4; ++t) {
        float ig = sigmoidf_(pri[t] + pbi[t]);
        float fg = sigmoidf_(prf[t] + pbf[t]);
        float og = sigmoidf_(pro[t] + pbo[t]);
        float s  = prs[t] + pbxs[t];
        float cand = prc[t] + pbxg[t] + pbhg[t];
        float gg = tanhf(s * cand);
        float c  = fg * pcp[t] + ig * gg;
        ph[t] = og * tanhf(c);
        pc[t] = c;
    }

    *(float4*)(out + (size_t)b * 1024 + j) = outh;
    *(float4*)(out + (size_t)BATCH * HID + (size_t)b * 1024 + j) = outc;
}

// ---------------- launch ----------------
extern "C" void kernel_launch(void* const* d_in, const int* in_sizes, int n_in,
                              void* d_out, int out_size)
{
    const float* x      = (const float*)d_in[0];
    const float* h_prev = (const float*)d_in[1];
    const float* c_prev = (const float*)d_in[2];
    const float* Wi     = (const float*)d_in[3];
    const float* bi     = (const float*)d_in[4];
    const float* Wf     = (const float*)d_in[5];
    const float* bf     = (const float*)d_in[6];
    const float* Wo     = (const float*)d_in[7];
    const float* bo     = (const float*)d_in[8];
    const float* Wxs    = (const float*)d_in[9];
    const float* bxs    = (const float*)d_in[10];
    const float* Wxg    = (const float*)d_in[11];
    const float* bxg    = (const float*)d_in[12];
    const float* Whg    = (const float*)d_in[13];
    const float* bhg    = (const float*)d_in[14];
    float* out = (float*)d_out;

    cudaFuncSetAttribute(gemm_kernel, cudaFuncAttributeMaxDynamicSharedMemorySize, SMEM_DYN);

    convA_kernel<<<(BATCH * KDIM / 4) / 256, 256>>>(x, h_prev);
    convB_kernel<<<(NV * KDIM / 4) / 256, 256>>>(Wi, Wf, Wo, Wxs, Wxg, Whg);

    dim3 grid(BATCH / BM, NV / BN);   // 32 x 40
    gemm_kernel<<<grid, 128, SMEM_DYN>>>();

    int total_vec = (BATCH * HID) / 4;
    srul_epilogue_kernel<<<(total_vec + 255) / 256, 256>>>(c_prev, bi, bf, bo, bxs, bxg, bhg, out);
}

// round 16
// speedup vs baseline: 2.2063x; 2.2063x over previous
#include <cuda_runtime.h>
#include <cuda_fp16.h>
#include <cstdint>
#include <math.h>

#define BATCH 4096
#define HID   1024
#define NV    5120          // virtual N: [0,3072)=i,f,o  [3072,4096)=cand  [4096,5120)=s
#define KDIM  2048
#define BM    128
#define BN    128
#define BK    32
#define NSTG  3

#define ROWH  40            // smem row stride in halves (64B data + 16B pad) -> 80B
#define TILE_BYTES (128 * ROWH * 2)          // 10240 per operand tile
#define STAGE_BYTES (2 * TILE_BYTES)         // A + B = 20480
#define SMEM_DYN (NSTG * STAGE_BYTES)        // 61440

// device scratch (static — no runtime allocation)
__device__ __half g_A[(size_t)BATCH * KDIM];    // 16 MB
__device__ __half g_B[(size_t)NV * KDIM];       // 20 MB
__device__ float  g_C[(size_t)BATCH * NV];      // 80 MB

// ---------------- helpers ----------------
__device__ __forceinline__ uint32_t smem_u32(const void* p) {
    uint32_t a;
    asm("{ .reg .u64 t; cvta.to.shared.u64 t, %1; cvt.u32.u64 %0, t; }" : "=r"(a) : "l"(p));
    return a;
}
__device__ __forceinline__ void cp_async16(uint32_t dst, const void* src) {
    asm volatile("cp.async.cg.shared.global [%0], [%1], 16;" :: "r"(dst), "l"(src));
}
__device__ __forceinline__ void cp_commit() { asm volatile("cp.async.commit_group;" ::: "memory"); }
__device__ __forceinline__ void cp_wait1()  { asm volatile("cp.async.wait_group 1;"  ::: "memory"); }

__device__ __forceinline__ void mma16816(float* c, const uint32_t* a, uint32_t b0, uint32_t b1) {
    asm volatile("mma.sync.aligned.m16n8k16.row.col.f32.f16.f16.f32 "
                 "{%0,%1,%2,%3}, {%4,%5,%6,%7}, {%8,%9}, {%0,%1,%2,%3};"
                 : "+f"(c[0]), "+f"(c[1]), "+f"(c[2]), "+f"(c[3])
                 : "r"(a[0]), "r"(a[1]), "r"(a[2]), "r"(a[3]), "r"(b0), "r"(b1));
}
__device__ __forceinline__ void ldsm_x4(uint32_t& r0, uint32_t& r1, uint32_t& r2, uint32_t& r3,
                                        uint32_t addr) {
    asm volatile("ldmatrix.sync.aligned.m8n8.x4.shared.b16 {%0,%1,%2,%3}, [%4];"
                 : "=r"(r0), "=r"(r1), "=r"(r2), "=r"(r3) : "r"(addr));
}

// ---------------- conversion kernels ----------------
__global__ __launch_bounds__(256) void convA_kernel(const float* __restrict__ x,
                                                    const float* __restrict__ h) {
    int idx = blockIdx.x * 256 + threadIdx.x;            // over (4096*2048)/4
    int v4 = idx * 4;
    if (v4 >= BATCH * KDIM) return;
    int m = v4 >> 11, k0 = v4 & 2047;
    float4 v = (k0 < 1024) ? *(const float4*)(x + (size_t)m * 1024 + k0)
                           : *(const float4*)(h + (size_t)m * 1024 + (k0 - 1024));
    __half2 p0 = __floats2half2_rn(v.x, v.y);
    __half2 p1 = __floats2half2_rn(v.z, v.w);
    *(__half2*)(g_A + (size_t)m * KDIM + k0)     = p0;
    *(__half2*)(g_A + (size_t)m * KDIM + k0 + 2) = p1;
}

__global__ __launch_bounds__(256) void convB_kernel(const float* __restrict__ Wi,
                                                    const float* __restrict__ Wf,
                                                    const float* __restrict__ Wo,
                                                    const float* __restrict__ Wxs,
                                                    const float* __restrict__ Wxg,
                                                    const float* __restrict__ Whg) {
    int idx = blockIdx.x * 256 + threadIdx.x;            // over (5120*2048)/4
    int v4 = idx * 4;
    if (v4 >= NV * KDIM) return;
    int n = v4 >> 11, k0 = v4 & 2047;
    float4 v;
    if (n < 3072) {
        const float* W = (n < 1024) ? Wi : (n < 2048) ? Wf : Wo;
        v = *(const float4*)(W + (size_t)(n & 1023) * 2048 + k0);
    } else if (n < 4096) {
        int rr = n - 3072;
        v = (k0 < 1024) ? *(const float4*)(Wxg + (size_t)rr * 1024 + k0)
                        : *(const float4*)(Whg + (size_t)rr * 1024 + (k0 - 1024));
    } else {
        int rr = n - 4096;
        v = (k0 < 1024) ? *(const float4*)(Wxs + (size_t)rr * 1024 + k0)
                        : make_float4(0.f, 0.f, 0.f, 0.f);
    }
    __half2 p0 = __floats2half2_rn(v.x, v.y);
    __half2 p1 = __floats2half2_rn(v.z, v.w);
    *(__half2*)(g_B + (size_t)n * KDIM + k0)     = p0;
    *(__half2*)(g_B + (size_t)n * KDIM + k0 + 2) = p1;
}

// ---------------- fp16 HMMA GEMM (round-10 structure + per-CTA K bound) ----------------
__global__ void __launch_bounds__(256, 2) gemm_kernel() {
    extern __shared__ char smem_dyn[];

    const int tid  = threadIdx.x;
    const int wid  = tid >> 5;
    const int lane = tid & 31;
    const int g    = lane >> 2;        // 0..7
    const int tig  = lane & 3;         // 0..3
    const int wm   = wid >> 1;         // 0..3 (rows wm*32)
    const int wn   = wid & 1;          // 0..1 (cols wn*64)
    const int bm0  = blockIdx.x * BM;
    const int n0   = blockIdx.y * BN;

    // s-region (n0 >= 4096) has true K = 1024; skip the zero-padded half.
    const int KT_local = (n0 >= 4096) ? 32 : 64;

    const uint32_t smem0 = smem_u32(smem_dyn);
    const int lrow = tid >> 1;                 // 0..127 : row loaded by this thread
    const int lch0 = (tid & 1) * 2;            // chunks {0,1} or {2,3}

    // ldmatrix lane addressing (byte offsets within a tile)
    const uint32_t a_lane_off = (uint32_t)((wm * 32 + (lane & 15)) * (ROWH * 2) + (lane >> 4) * 16);
    const uint32_t b_lane_off = (uint32_t)((wn * 64 + ((lane >> 4) << 3) + (lane & 7)) * (ROWH * 2)
                                           + (((lane >> 3) & 1) * 16));

    // stage loader: tile `kk` into slot `s` (each thread: 2 chunks A + 2 chunks B)
    auto load_stage = [&](int s, int kk) {
        int kcol = kk * BK;
        uint32_t baseA = smem0 + s * STAGE_BYTES;
        uint32_t baseB = baseA + TILE_BYTES;
        const __half* srcA = g_A + (size_t)(bm0 + lrow) * KDIM + kcol;
        const __half* srcB = g_B + (size_t)(n0  + lrow) * KDIM + kcol;
        uint32_t rowoff = lrow * (ROWH * 2);
        #pragma unroll
        for (int c = 0; c < 2; ++c) {
            int ch = lch0 + c;
            cp_async16(baseA + rowoff + ch * 16, srcA + ch * 8);
            cp_async16(baseB + rowoff + ch * 16, srcB + ch * 8);
        }
        cp_commit();
    };

    float acc[2][8][4];
    #pragma unroll
    for (int i = 0; i < 2; ++i)
        #pragma unroll
        for (int j = 0; j < 8; ++j)
            #pragma unroll
            for (int t = 0; t < 4; ++t) acc[i][j][t] = 0.f;

    // prologue: stages 0,1
    load_stage(0, 0);
    load_stage(1, 1);

    for (int it = 0; it < KT_local; ++it) {
        int s = it % NSTG;
        cp_wait1();             // stage `it` resident (this thread's chunks)
        __syncthreads();        // all threads' chunks visible; prev compute done

        if (it + 2 < KT_local) load_stage((it + 2) % NSTG, it + 2);
        else cp_commit();       // keep group accounting exact at tail

        uint32_t Asb = smem0 + s * STAGE_BYTES;
        uint32_t Bsb = Asb + TILE_BYTES;

        #pragma unroll
        for (int ks = 0; ks < 2; ++ks) {
            const uint32_t kboff = ks * 32;      // 16 halves = 32 bytes
            uint32_t a[2][4];
            ldsm_x4(a[0][0], a[0][1], a[0][2], a[0][3], Asb + a_lane_off + kboff);
            ldsm_x4(a[1][0], a[1][1], a[1][2], a[1][3], Asb + a_lane_off + 16 * (ROWH * 2) + kboff);
            #pragma unroll
            for (int j = 0; j < 4; ++j) {        // two n-tiles per ldmatrix
                uint32_t b0, b1, b2, b3;
                ldsm_x4(b0, b1, b2, b3, Bsb + b_lane_off + j * 16 * (ROWH * 2) + kboff);
                #pragma unroll
                for (int im = 0; im < 2; ++im) {
                    mma16816(acc[im][2 * j],     a[im], b0, b1);
                    mma16816(acc[im][2 * j + 1], a[im], b2, b3);
                }
            }
        }
    }

    // write C tile
    #pragma unroll
    for (int im = 0; im < 2; ++im) {
        #pragma unroll
        for (int in = 0; in < 8; ++in) {
            int row = bm0 + wm * 32 + im * 16 + g;
            int col = n0 + wn * 64 + in * 8 + 2 * tig;
            float2 v0 = make_float2(acc[im][in][0], acc[im][in][1]);
            float2 v1 = make_float2(acc[im][in][2], acc[im][in][3]);
            *(float2*)(g_C + (size_t)row * NV + col)       = v0;
            *(float2*)(g_C + (size_t)(row + 8) * NV + col) = v1;
        }
    }
}

// ---------------- fused epilogue ----------------
__device__ __forceinline__ float sigmoidf_(float v) { return 1.0f / (1.0f + expf(-v)); }

__global__ __launch_bounds__(256)
void srul_epilogue_kernel(const float* __restrict__ c_prev,
                          const float* __restrict__ bi,
                          const float* __restrict__ bf,
                          const float* __restrict__ bo,
                          const float* __restrict__ bxs,
                          const float* __restrict__ bxg,
                          const float* __restrict__ bhg,
                          float* __restrict__ out)
{
    int idx = blockIdx.x * blockDim.x + threadIdx.x;
    int v = idx * 4;
    if (v >= BATCH * HID) return;
    int b = v >> 10;
    int j = v & 1023;

    const float* row = g_C + (size_t)b * NV;
    float4 ri = *(const float4*)(row + j);
    float4 rf = *(const float4*)(row + 1024 + j);
    float4 ro = *(const float4*)(row + 2048 + j);
    float4 rc = *(const float4*)(row + 3072 + j);
    float4 rs = *(const float4*)(row + 4096 + j);
    float4 vbi  = *(const float4*)(bi + j);
    float4 vbf  = *(const float4*)(bf + j);
    float4 vbo  = *(const float4*)(bo + j);
    float4 vbxs = *(const float4*)(bxs + j);
    float4 vbxg = *(const float4*)(bxg + j);
    float4 vbhg = *(const float4*)(bhg + j);
    float4 vcp  = *(const float4*)(c_prev + (size_t)b * 1024 + j);

    float4 outh, outc;
    const float* pri = &ri.x; const float* prf = &rf.x; const float* pro = &ro.x;
    const float* prc = &rc.x; const float* prs = &rs.x;
    const float* pbi = &vbi.x; const float* pbf = &vbf.x; const float* pbo = &vbo.x;
    const float* pbxs = &vbxs.x; const float* pbxg = &vbxg.x; const float* pbhg = &vbhg.x;
    const float* pcp = &vcp.x;
    float* ph = &outh.x; float* pc = &outc.x;

    #pragma unroll
    for (int t = 0; t < 4; ++t) {
        float ig = sigmoidf_(pri[t] + pbi[t]);
        float fg = sigmoidf_(prf[t] + pbf[t]);
        float og = sigmoidf_(pro[t] + pbo[t]);
        float s  = prs[t] + pbxs[t];
        float cand = prc[t] + pbxg[t] + pbhg[t];
        float gg = tanhf(s * cand);
        float c  = fg * pcp[t] + ig * gg;
        ph[t] = og * tanhf(c);
        pc[t] = c;
    }

    *(float4*)(out + (size_t)b * 1024 + j) = outh;
    *(float4*)(out + (size_t)BATCH * HID + (size_t)b * 1024 + j) = outc;
}

// ---------------- launch ----------------
extern "C" void kernel_launch(void* const* d_in, const int* in_sizes, int n_in,
                              void* d_out, int out_size)
{
    const float* x      = (const float*)d_in[0];
    const float* h_prev = (const float*)d_in[1];
    const float* c_prev = (const float*)d_in[2];
    const float* Wi     = (const float*)d_in[3];
    const float* bi     = (const float*)d_in[4];
    const float* Wf     = (const float*)d_in[5];
    const float* bf     = (const float*)d_in[6];
    const float* Wo     = (const float*)d_in[7];
    const float* bo     = (const float*)d_in[8];
    const float* Wxs    = (const float*)d_in[9];
    const float* bxs    = (const float*)d_in[10];
    const float* Wxg    = (const float*)d_in[11];
    const float* bxg    = (const float*)d_in[12];
    const float* Whg    = (const float*)d_in[13];
    const float* bhg    = (const float*)d_in[14];
    float* out = (float*)d_out;

    cudaFuncSetAttribute(gemm_kernel, cudaFuncAttributeMaxDynamicSharedMemorySize, SMEM_DYN);

    convA_kernel<<<(BATCH * KDIM / 4) / 256, 256>>>(x, h_prev);
    convB_kernel<<<(NV * KDIM / 4) / 256, 256>>>(Wi, Wf, Wo, Wxs, Wxg, Whg);

    dim3 grid(BATCH / BM, NV / BN);   // 32 x 40
    gemm_kernel<<<grid, 256, SMEM_DYN>>>();

    int total_vec = (BATCH * HID) / 4;
    srul_epilogue_kernel<<<(total_vec + 255) / 256, 256>>>(c_prev, bi, bf, bo, bxs, bxg, bhg, out);
}

// round 17
// speedup vs baseline: 2.2391x; 1.0149x over previous
#include <cuda_runtime.h>
#include <cuda_fp16.h>
#include <cstdint>
#include <math.h>

#define BATCH 4096
#define HID   1024
#define NV    5120          // virtual N: [0,3072)=i,f,o  [3072,4096)=cand  [4096,5120)=s
#define KDIM  2048
#define BM    128
#define BN    128
#define BK    32
#define NSTG  3

#define ROWH  40            // smem row stride in halves (64B data + 16B pad) -> 80B
#define TILE_BYTES (128 * ROWH * 2)          // 10240 per operand tile
#define STAGE_BYTES (2 * TILE_BYTES)         // A + B = 20480
#define SMEM_DYN (NSTG * STAGE_BYTES)        // 61440

// device scratch (static — no runtime allocation)
__device__ __half g_A[(size_t)BATCH * KDIM];    // 16 MB
__device__ __half g_B[(size_t)NV * KDIM];       // 20 MB
__device__ __half g_C[(size_t)BATCH * NV];      // 40 MB (fp16 preacts)

// ---------------- helpers ----------------
__device__ __forceinline__ uint32_t smem_u32(const void* p) {
    uint32_t a;
    asm("{ .reg .u64 t; cvta.to.shared.u64 t, %1; cvt.u32.u64 %0, t; }" : "=r"(a) : "l"(p));
    return a;
}
__device__ __forceinline__ void cp_async16(uint32_t dst, const void* src) {
    asm volatile("cp.async.cg.shared.global [%0], [%1], 16;" :: "r"(dst), "l"(src));
}
__device__ __forceinline__ void cp_commit() { asm volatile("cp.async.commit_group;" ::: "memory"); }
__device__ __forceinline__ void cp_wait1()  { asm volatile("cp.async.wait_group 1;"  ::: "memory"); }

__device__ __forceinline__ void mma16816(float* c, const uint32_t* a, uint32_t b0, uint32_t b1) {
    asm volatile("mma.sync.aligned.m16n8k16.row.col.f32.f16.f16.f32 "
                 "{%0,%1,%2,%3}, {%4,%5,%6,%7}, {%8,%9}, {%0,%1,%2,%3};"
                 : "+f"(c[0]), "+f"(c[1]), "+f"(c[2]), "+f"(c[3])
                 : "r"(a[0]), "r"(a[1]), "r"(a[2]), "r"(a[3]), "r"(b0), "r"(b1));
}
__device__ __forceinline__ void ldsm_x4(uint32_t& r0, uint32_t& r1, uint32_t& r2, uint32_t& r3,
                                        uint32_t addr) {
    asm volatile("ldmatrix.sync.aligned.m8n8.x4.shared.b16 {%0,%1,%2,%3}, [%4];"
                 : "=r"(r0), "=r"(r1), "=r"(r2), "=r"(r3) : "r"(addr));
}
__device__ __forceinline__ float4 ld_h4(const __half* p) {
    __half2 a = *(const __half2*)p;
    __half2 b = *(const __half2*)(p + 2);
    float2 fa = __half22float2(a), fb = __half22float2(b);
    return make_float4(fa.x, fa.y, fb.x, fb.y);
}

// ---------------- merged conversion kernel ----------------
// blocks [0, ABLK): A-side (4096x2048/4 elems). blocks [ABLK, ABLK+BBLK): B-side.
#define ABLK ((BATCH * KDIM / 4) / 256)      // 8192
#define BBLK ((NV * KDIM / 4) / 256)         // 10240

__global__ __launch_bounds__(256) void conv_kernel(const float* __restrict__ x,
                                                   const float* __restrict__ h,
                                                   const float* __restrict__ Wi,
                                                   const float* __restrict__ Wf,
                                                   const float* __restrict__ Wo,
                                                   const float* __restrict__ Wxs,
                                                   const float* __restrict__ Wxg,
                                                   const float* __restrict__ Whg) {
    int bid = blockIdx.x;
    if (bid < ABLK) {
        int v4 = (bid * 256 + threadIdx.x) * 4;
        int m = v4 >> 11, k0 = v4 & 2047;
        float4 v = (k0 < 1024) ? *(const float4*)(x + (size_t)m * 1024 + k0)
                               : *(const float4*)(h + (size_t)m * 1024 + (k0 - 1024));
        *(__half2*)(g_A + (size_t)m * KDIM + k0)     = __floats2half2_rn(v.x, v.y);
        *(__half2*)(g_A + (size_t)m * KDIM + k0 + 2) = __floats2half2_rn(v.z, v.w);
    } else {
        int v4 = ((bid - ABLK) * 256 + threadIdx.x) * 4;
        int n = v4 >> 11, k0 = v4 & 2047;
        float4 v;
        if (n < 3072) {
            const float* W = (n < 1024) ? Wi : (n < 2048) ? Wf : Wo;
            v = *(const float4*)(W + (size_t)(n & 1023) * 2048 + k0);
        } else if (n < 4096) {
            int rr = n - 3072;
            v = (k0 < 1024) ? *(const float4*)(Wxg + (size_t)rr * 1024 + k0)
                            : *(const float4*)(Whg + (size_t)rr * 1024 + (k0 - 1024));
        } else {
            int rr = n - 4096;
            v = (k0 < 1024) ? *(const float4*)(Wxs + (size_t)rr * 1024 + k0)
                            : make_float4(0.f, 0.f, 0.f, 0.f);
        }
        *(__half2*)(g_B + (size_t)n * KDIM + k0)     = __floats2half2_rn(v.x, v.y);
        *(__half2*)(g_B + (size_t)n * KDIM + k0 + 2) = __floats2half2_rn(v.z, v.w);
    }
}

// ---------------- fp16 HMMA GEMM (per-CTA K bound, fp16 C) ----------------
__global__ void __launch_bounds__(256, 2) gemm_kernel() {
    extern __shared__ char smem_dyn[];

    const int tid  = threadIdx.x;
    const int wid  = tid >> 5;
    const int lane = tid & 31;
    const int g    = lane >> 2;        // 0..7
    const int tig  = lane & 3;         // 0..3
    const int wm   = wid >> 1;         // 0..3 (rows wm*32)
    const int wn   = wid & 1;          // 0..1 (cols wn*64)
    const int bm0  = blockIdx.x * BM;
    const int n0   = blockIdx.y * BN;

    // s-region (n0 >= 4096) has true K = 1024; skip the zero-padded half.
    const int KT_local = (n0 >= 4096) ? 32 : 64;

    const uint32_t smem0 = smem_u32(smem_dyn);
    const int lrow = tid >> 1;                 // 0..127 : row loaded by this thread
    const int lch0 = (tid & 1) * 2;            // chunks {0,1} or {2,3}

    // ldmatrix lane addressing (byte offsets within a tile)
    const uint32_t a_lane_off = (uint32_t)((wm * 32 + (lane & 15)) * (ROWH * 2) + (lane >> 4) * 16);
    const uint32_t b_lane_off = (uint32_t)((wn * 64 + ((lane >> 4) << 3) + (lane & 7)) * (ROWH * 2)
                                           + (((lane >> 3) & 1) * 16));

    // stage loader: tile `kk` into slot `s` (each thread: 2 chunks A + 2 chunks B)
    auto load_stage = [&](int s, int kk) {
        int kcol = kk * BK;
        uint32_t baseA = smem0 + s * STAGE_BYTES;
        uint32_t baseB = baseA + TILE_BYTES;
        const __half* srcA = g_A + (size_t)(bm0 + lrow) * KDIM + kcol;
        const __half* srcB = g_B + (size_t)(n0  + lrow) * KDIM + kcol;
        uint32_t rowoff = lrow * (ROWH * 2);
        #pragma unroll
        for (int c = 0; c < 2; ++c) {
            int ch = lch0 + c;
            cp_async16(baseA + rowoff + ch * 16, srcA + ch * 8);
            cp_async16(baseB + rowoff + ch * 16, srcB + ch * 8);
        }
        cp_commit();
    };

    float acc[2][8][4];
    #pragma unroll
    for (int i = 0; i < 2; ++i)
        #pragma unroll
        for (int j = 0; j < 8; ++j)
            #pragma unroll
            for (int t = 0; t < 4; ++t) acc[i][j][t] = 0.f;

    // prologue: stages 0,1
    load_stage(0, 0);
    load_stage(1, 1);

    for (int it = 0; it < KT_local; ++it) {
        int s = it % NSTG;
        cp_wait1();             // stage `it` resident (this thread's chunks)
        __syncthreads();        // all threads' chunks visible; prev compute done

        if (it + 2 < KT_local) load_stage((it + 2) % NSTG, it + 2);
        else cp_commit();       // keep group accounting exact at tail

        uint32_t Asb = smem0 + s * STAGE_BYTES;
        uint32_t Bsb = Asb + TILE_BYTES;

        #pragma unroll
        for (int ks = 0; ks < 2; ++ks) {
            const uint32_t kboff = ks * 32;      // 16 halves = 32 bytes
            uint32_t a[2][4];
            ldsm_x4(a[0][0], a[0][1], a[0][2], a[0][3], Asb + a_lane_off + kboff);
            ldsm_x4(a[1][0], a[1][1], a[1][2], a[1][3], Asb + a_lane_off + 16 * (ROWH * 2) + kboff);
            #pragma unroll
            for (int j = 0; j < 4; ++j) {        // two n-tiles per ldmatrix
                uint32_t b0, b1, b2, b3;
                ldsm_x4(b0, b1, b2, b3, Bsb + b_lane_off + j * 16 * (ROWH * 2) + kboff);
                #pragma unroll
                for (int im = 0; im < 2; ++im) {
                    mma16816(acc[im][2 * j],     a[im], b0, b1);
                    mma16816(acc[im][2 * j + 1], a[im], b2, b3);
                }
            }
        }
    }

    // write C tile (fp16)
    #pragma unroll
    for (int im = 0; im < 2; ++im) {
        #pragma unroll
        for (int in = 0; in < 8; ++in) {
            int row = bm0 + wm * 32 + im * 16 + g;
            int col = n0 + wn * 64 + in * 8 + 2 * tig;
            *(__half2*)(g_C + (size_t)row * NV + col) =
                __floats2half2_rn(acc[im][in][0], acc[im][in][1]);
            *(__half2*)(g_C + (size_t)(row + 8) * NV + col) =
                __floats2half2_rn(acc[im][in][2], acc[im][in][3]);
        }
    }
}

// ---------------- fused epilogue ----------------
__device__ __forceinline__ float sigmoidf_(float v) { return 1.0f / (1.0f + expf(-v)); }

__global__ __launch_bounds__(256)
void srul_epilogue_kernel(const float* __restrict__ c_prev,
                          const float* __restrict__ bi,
                          const float* __restrict__ bf,
                          const float* __restrict__ bo,
                          const float* __restrict__ bxs,
                          const float* __restrict__ bxg,
                          const float* __restrict__ bhg,
                          float* __restrict__ out)
{
    int idx = blockIdx.x * blockDim.x + threadIdx.x;
    int v = idx * 4;
    if (v >= BATCH * HID) return;
    int b = v >> 10;
    int j = v & 1023;

    const __half* row = g_C + (size_t)b * NV;
    float4 ri = ld_h4(row + j);
    float4 rf = ld_h4(row + 1024 + j);
    float4 ro = ld_h4(row + 2048 + j);
    float4 rc = ld_h4(row + 3072 + j);
    float4 rs = ld_h4(row + 4096 + j);
    float4 vbi  = *(const float4*)(bi + j);
    float4 vbf  = *(const float4*)(bf + j);
    float4 vbo  = *(const float4*)(bo + j);
    float4 vbxs = *(const float4*)(bxs + j);
    float4 vbxg = *(const float4*)(bxg + j);
    float4 vbhg = *(const float4*)(bhg + j);
    float4 vcp  = *(const float4*)(c_prev + (size_t)b * 1024 + j);

    float4 outh, outc;
    const float* pri = &ri.x; const float* prf = &rf.x; const float* pro = &ro.x;
    const float* prc = &rc.x; const float* prs = &rs.x;
    const float* pbi = &vbi.x; const float* pbf = &vbf.x; const float* pbo = &vbo.x;
    const float* pbxs = &vbxs.x; const float* pbxg = &vbxg.x; const float* pbhg = &vbhg.x;
    const float* pcp = &vcp.x;
    float* ph = &outh.x; float* pc = &outc.x;

    #pragma unroll
    for (int t = 0; t < 4; ++t) {
        float ig = sigmoidf_(pri[t] + pbi[t]);
        float fg = sigmoidf_(prf[t] + pbf[t]);
        float og = sigmoidf_(pro[t] + pbo[t]);
        float s  = prs[t] + pbxs[t];
        float cand = prc[t] + pbxg[t] + pbhg[t];
        float gg = tanhf(s * cand);
        float c  = fg * pcp[t] + ig * gg;
        ph[t] = og * tanhf(c);
        pc[t] = c;
    }

    *(float4*)(out + (size_t)b * 1024 + j) = outh;
    *(float4*)(out + (size_t)BATCH * HID + (size_t)b * 1024 + j) = outc;
}

// ---------------- launch ----------------
extern "C" void kernel_launch(void* const* d_in, const int* in_sizes, int n_in,
                              void* d_out, int out_size)
{
    const float* x      = (const float*)d_in[0];
    const float* h_prev = (const float*)d_in[1];
    const float* c_prev = (const float*)d_in[2];
    const float* Wi     = (const float*)d_in[3];
    const float* bi     = (const float*)d_in[4];
    const float* Wf     = (const float*)d_in[5];
    const float* bf     = (const float*)d_in[6];
    const float* Wo     = (const float*)d_in[7];
    const float* bo     = (const float*)d_in[8];
    const float* Wxs    = (const float*)d_in[9];
    const float* bxs    = (const float*)d_in[10];
    const float* Wxg    = (const float*)d_in[11];
    const float* bxg    = (const float*)d_in[12];
    const float* Whg    = (const float*)d_in[13];
    const float* bhg    = (const float*)d_in[14];
    float* out = (float*)d_out;

    cudaFuncSetAttribute(gemm_kernel, cudaFuncAttributeMaxDynamicSharedMemorySize, SMEM_DYN);

    conv_kernel<<<ABLK + BBLK, 256>>>(x, h_prev, Wi, Wf, Wo, Wxs, Wxg, Whg);

    dim3 grid(BATCH / BM, NV / BN);   // 32 x 40
    gemm_kernel<<<grid, 256, SMEM_DYN>>>();

    int total_vec = (BATCH * HID) / 4;
    srul_epilogue_kernel<<<(total_vec + 255) / 256, 256>>>(c_prev, bi, bf, bo, bxs, bxg, bhg, out);
}